// round 13
// baseline (speedup 1.0000x reference)
#include <cuda_runtime.h>

// out[b,t,d] = x[b,t,d] * (sum_{k<t} x[b,k,d])
// B=8, T=4096, D=1024, fp32.
// Single-pass, register-staged, float2-vectorized, software-pipelined:
// next stage's loads are interleaved into the current stage's emit loop, so
// LDGs are in flight across the barrier+scan window (previously dead time).
// DRAM traffic = 1 read + 1 write = 268 MB.

#define T_DIM   4096
#define D_DIM   1024
#define VLANES  8                        // float2 lanes per slice-row
#define D_TILE  (VLANES * 2)             // 16 d per block
#define SLICES  32
#define CHUNK   16                       // t-steps per thread per stage
#define STAGE_T (SLICES * CHUNK)         // 512
#define NSTAGE  (T_DIM / STAGE_T)        // 8
#define NTHREADS (VLANES * SLICES)       // 256
#define ROW2    (D_DIM / 2)              // row stride in float2 units

__global__ __launch_bounds__(NTHREADS, 4)
void siso_scan_pf(const float2* __restrict__ x, float2* __restrict__ out) {
    __shared__ float ssum[SLICES][D_TILE + 1];  // [slice][d], stride 17
    __shared__ float carry[D_TILE];             // running prefix per d

    const int tid    = threadIdx.x;
    const int lane_v = tid & (VLANES - 1);      // float2 lane (0..7)
    const int slice  = tid >> 3;                // t-slice (0..31)
    const int wid    = tid >> 5;                // warp id (0..7)
    const int lid    = tid & 31;

    const int d_tiles = D_DIM / D_TILE;         // 64
    const int d_tile  = blockIdx.x & (d_tiles - 1);
    const int b       = blockIdx.x >> 6;

    // base in float2 units; per-thread start of its chunk in stage 0
    const unsigned base = (unsigned)b * (T_DIM * ROW2)
                        + (unsigned)d_tile * VLANES + (unsigned)lane_v
                        + (unsigned)slice * CHUNK * ROW2;

    const float2* __restrict__ p = x   + base;
    float2*       __restrict__ q = out + base;

    if (tid < D_TILE) carry[tid] = 0.f;
    // (carry written before first scan read; first __syncthreads below covers it)

    // Prologue: load stage 0 chunk into registers (16 independent LDG.64).
    float2 v[CHUNK];
    #pragma unroll
    for (int i = 0; i < CHUNK; ++i) {
        v[i] = p[(unsigned)i * ROW2];
    }

    for (int st = 0; st < NSTAGE; ++st) {
        // Chunk sums (consumes this stage's loads — they were issued a full
        // emit+barrier+scan window ago except for stage 0).
        float sx = 0.f, sy = 0.f;
        #pragma unroll
        for (int i = 0; i < CHUNK; ++i) {
            sx += v[i].x;
            sy += v[i].y;
        }
        ssum[slice][lane_v * 2]     = sx;
        ssum[slice][lane_v * 2 + 1] = sy;
        __syncthreads();

        // Each warp shuffle-scans 2 d-columns (32 slice sums each).
        #pragma unroll
        for (int cc = 0; cc < 2; ++cc) {
            const int col = wid * 2 + cc;
            float val  = ssum[lid][col];
            float incl = val;
            #pragma unroll
            for (int off = 1; off < 32; off <<= 1) {
                float n = __shfl_up_sync(0xFFFFFFFFu, incl, off);
                if (lid >= off) incl += n;
            }
            float c = carry[col];
            ssum[lid][col] = (incl - val) + c;       // exclusive + carry-in
            if (lid == 31) carry[col] = incl + c;    // carry-out
        }
        __syncthreads();

        // Emit + prefetch: consume v[i], immediately reload it from the next
        // stage. Next-stage LDGs issue during the STG stream and stay in
        // flight across the next barrier+scan.
        float rx = ssum[slice][lane_v * 2];
        float ry = ssum[slice][lane_v * 2 + 1];
        const bool more = (st + 1 < NSTAGE);
        const float2* __restrict__ pn = p + (unsigned)(STAGE_T * ROW2);
        #pragma unroll
        for (int i = 0; i < CHUNK; ++i) {
            float2 cur = v[i];
            if (more) v[i] = pn[(unsigned)i * ROW2];   // predicated LDG
            float2 o;
            o.x = cur.x * rx;
            o.y = cur.y * ry;
            q[(unsigned)i * ROW2] = o;
            rx += cur.x;
            ry += cur.y;
        }
        p = pn;
        q += (unsigned)(STAGE_T * ROW2);
        // ssum/carry only rewritten after the next in-loop __syncthreads().
    }
}

extern "C" void kernel_launch(void* const* d_in, const int* in_sizes, int n_in,
                              void* d_out, int out_size) {
    const float2* x = (const float2*)d_in[0];
    float2* out = (float2*)d_out;

    const int n = in_sizes[0];                    // B*T*D
    const int B = n / (T_DIM * D_DIM);            // 8
    const int blocks = B * (D_DIM / D_TILE);      // 512

    siso_scan_pf<<<blocks, NTHREADS>>>(x, out);
}